// round 6
// baseline (speedup 1.0000x reference)
#include <cuda_runtime.h>
#include <math.h>

// Problem constants
#define NB   16            // batch
#define SQ   256           // sequence
#define MM   768           // model dim
#define TK   10            // stages
#define ROWS (NB*SQ)       // 4096 fused (n, j) rows
#define HID  (4*MM)        // 3072
#define EPS  1e-5f

// ---------------- static scratch (allocation-free rule) ----------------
__device__ float g_s  [ROWS*MM];   // state
__device__ float g_sn [ROWS*MM];   // LN output / t buffer
__device__ float g_v  [ROWS*MM];   // per-stage v
__device__ float g_imv[ROWS*MM];   // exclusive prefix of v
__device__ float g_h  [ROWS*HID];  // MLP hidden
__device__ float g_pe [SQ*MM];     // positional encoding

// ---------------- positional encoding (float64, matches reference) ----
__global__ void pe_kernel(float* __restrict__ pe) {
    int idx = blockIdx.x * 256 + threadIdx.x;
    if (idx >= SQ * MM) return;
    int j = idx / MM;
    int m = idx % MM;
    int z = m & ~1;  // even floor
    double ang = (double)j * exp(-((double)(2 * z) / (double)MM) * log(10000.0));
    pe[idx] = (float)((m & 1) ? cos(ang) : sin(ang));
}

// ---------------- LayerNorm (+optional residual add) ------------------
// one block per row, 256 threads, 3 elements/thread (768 = 3*256)
template <bool ADDRES>
__global__ __launch_bounds__(256) void ln_kernel(
    const float* __restrict__ in, const float* __restrict__ g,
    const float* __restrict__ b, float* __restrict__ out)
{
    int r = blockIdx.x;
    int tid = threadIdx.x;
    const float* row = in + (size_t)r * MM;
    float x0 = row[tid], x1 = row[tid + 256], x2 = row[tid + 512];

    __shared__ float sd[256];
    sd[tid] = x0 + x1 + x2;
    __syncthreads();
    #pragma unroll
    for (int o = 128; o > 0; o >>= 1) {
        if (tid < o) sd[tid] += sd[tid + o];
        __syncthreads();
    }
    float mu = sd[0] * (1.0f / (float)MM);
    __syncthreads();

    float d0 = x0 - mu, d1 = x1 - mu, d2 = x2 - mu;
    sd[tid] = d0 * d0 + d1 * d1 + d2 * d2;
    __syncthreads();
    #pragma unroll
    for (int o = 128; o > 0; o >>= 1) {
        if (tid < o) sd[tid] += sd[tid + o];
        __syncthreads();
    }
    float var  = sd[0] * (1.0f / (float)MM);
    float rstd = 1.0f / sqrtf(var + EPS);

    float* orow = out + (size_t)r * MM;
    orow[tid]       = d0 * rstd * g[tid]       + b[tid]       + (ADDRES ? x0 : 0.f);
    orow[tid + 256] = d1 * rstd * g[tid + 256] + b[tid + 256] + (ADDRES ? x1 : 0.f);
    orow[tid + 512] = d2 * rstd * g[tid + 512] + b[tid + 512] + (ADDRES ? x2 : 0.f);
}

// ---------------- exclusive prefix sum over tokens ---------------------
// chains: (n, d) -> 16*768 = 12288 threads; row stride MM, length SQ.
__global__ __launch_bounds__(256) void scan_kernel(
    const float* __restrict__ v, float* __restrict__ imv)
{
    int idx = blockIdx.x * 256 + threadIdx.x;     // 0..12287
    int n = idx / MM;
    int d = idx % MM;
    const float* src = v   + (size_t)n * SQ * MM + d;
    float*       dst = imv + (size_t)n * SQ * MM + d;
    float acc = 0.f;
    #pragma unroll 8
    for (int j = 0; j < SQ; j++) {
        dst[(size_t)j * MM] = acc;
        acc += src[(size_t)j * MM];
    }
}

// ---------------- tiled SGEMM: C = A(Mr,K) @ W(Nc,K)^T [+ epilogue] ----
// BM=128, BN=64, BK=16, 256 threads, 8x4 per-thread microkernel.
// All dims here are multiples of the tiles (4096 | 768 | 3072), no bounds.
template <bool BIAS, bool RESID, bool GELUF, bool PEB>
__global__ __launch_bounds__(256) void sgemm_tn(
    const float* __restrict__ A, const float* __restrict__ W,
    const float* __restrict__ bias, const float* __restrict__ pe,
    float* __restrict__ C, const float* __restrict__ resid,
    int Mr, int Nc, int K)
{
    constexpr int BM = 128, BN = 64, BK = 16;
    __shared__ float As[BK][BM + 4];
    __shared__ float Bs[BK][BN + 4];

    int tid = threadIdx.x;
    int bx = blockIdx.x;   // column tile
    int by = blockIdx.y;   // row tile
    int tx = tid & 15;     // cols tx*4
    int ty = tid >> 4;     // rows ty*8

    const float* Ab = A + (size_t)(by * BM) * K;
    const float* Wb = W + (size_t)(bx * BN) * K;

    float acc[8][4];
    #pragma unroll
    for (int i = 0; i < 8; i++)
        #pragma unroll
        for (int j = 0; j < 4; j++) acc[i][j] = 0.f;

    for (int kk = 0; kk < K; kk += BK) {
        // --- load A tile: 128x16 = 512 float4, 2 per thread
        #pragma unroll
        for (int L = 0; L < 2; L++) {
            int q   = tid + L * 256;
            int row = q >> 2;
            int kq  = q & 3;
            float4 vA = *(const float4*)(Ab + (size_t)row * K + kk + kq * 4);
            As[kq * 4 + 0][row] = vA.x;
            As[kq * 4 + 1][row] = vA.y;
            As[kq * 4 + 2][row] = vA.z;
            As[kq * 4 + 3][row] = vA.w;
        }
        // --- load W tile: 64x16 = 256 float4, 1 per thread
        {
            int row = tid >> 2;
            int kq  = tid & 3;
            float4 vB = *(const float4*)(Wb + (size_t)row * K + kk + kq * 4);
            Bs[kq * 4 + 0][row] = vB.x;
            Bs[kq * 4 + 1][row] = vB.y;
            Bs[kq * 4 + 2][row] = vB.z;
            Bs[kq * 4 + 3][row] = vB.w;
        }
        __syncthreads();

        #pragma unroll
        for (int k = 0; k < BK; k++) {
            float4 a0 = *(const float4*)&As[k][ty * 8];
            float4 a1 = *(const float4*)&As[k][ty * 8 + 4];
            float4 b0 = *(const float4*)&Bs[k][tx * 4];
            float ar[8] = {a0.x, a0.y, a0.z, a0.w, a1.x, a1.y, a1.z, a1.w};
            float br[4] = {b0.x, b0.y, b0.z, b0.w};
            #pragma unroll
            for (int i = 0; i < 8; i++)
                #pragma unroll
                for (int j = 0; j < 4; j++)
                    acc[i][j] = fmaf(ar[i], br[j], acc[i][j]);
        }
        __syncthreads();
    }

    // --- epilogue
    int c_row0 = by * BM + ty * 8;
    int c_col0 = bx * BN + tx * 4;
    #pragma unroll
    for (int i = 0; i < 8; i++) {
        int r = c_row0 + i;
        float* Crow = C + (size_t)r * Nc + c_col0;
        #pragma unroll
        for (int j = 0; j < 4; j++) {
            float val = acc[i][j];
            if (BIAS)  val += bias[c_col0 + j];
            if (PEB)   val += pe[(size_t)(r & (SQ - 1)) * MM + c_col0 + j];
            if (RESID) val += resid[(size_t)r * Nc + c_col0 + j];
            if (GELUF) val = 0.5f * val * (1.0f + erff(val * 0.70710678118654752f));
            Crow[j] = val;
        }
    }
}

// ---------------- launcher ---------------------------------------------
extern "C" void kernel_launch(void* const* d_in, const int* in_sizes, int n_in,
                              void* d_out, int out_size)
{
    (void)in_sizes; (void)n_in; (void)out_size;
    const float* x      = (const float*)d_in[0];
    const float* weight = (const float*)d_in[1];
    // d_in[2] = Wq, d_in[3] = Wk: provably dead (softmax over size-1 axis == 1)
    const float* Wv     = (const float*)d_in[4];   // (TK,1,768,768)
    const float* Wo     = (const float*)d_in[5];   // (TK,768,768)
    const float* ln1_g  = (const float*)d_in[6];
    const float* ln1_b  = (const float*)d_in[7];
    const float* ln2_g  = (const float*)d_in[8];
    const float* ln2_b  = (const float*)d_in[9];
    const float* fc1_w  = (const float*)d_in[10];  // (3072,768)
    const float* fc1_b  = (const float*)d_in[11];
    const float* fc2_w  = (const float*)d_in[12];  // (768,3072)
    const float* fc2_b  = (const float*)d_in[13];
    float* out = (float*)d_out;

    float *s, *sn, *v, *imv, *h, *pe;
    cudaGetSymbolAddress((void**)&s,   g_s);
    cudaGetSymbolAddress((void**)&sn,  g_sn);
    cudaGetSymbolAddress((void**)&v,   g_v);
    cudaGetSymbolAddress((void**)&imv, g_imv);
    cudaGetSymbolAddress((void**)&h,   g_h);
    cudaGetSymbolAddress((void**)&pe,  g_pe);

    dim3 g768(MM / 64, ROWS / 128);    // (12, 32)
    dim3 g3072(HID / 64, ROWS / 128);  // (48, 32)

    // positional encoding (fp64, once per launch)
    pe_kernel<<<(SQ * MM + 255) / 256, 256>>>(pe);

    // prelude: s = x @ weight^T + PE
    sgemm_tn<false, false, false, true><<<g768, 256>>>(
        x, weight, nullptr, pe, s, nullptr, ROWS, MM, MM);

    // 10 sequential stages, each fully parallel over all (n, j) rows.
    for (int a = 0; a < TK; a++) {
        const float* Wv_a = Wv + (size_t)a * MM * MM;
        const float* Wo_a = Wo + (size_t)a * MM * MM;

        // sn = LN1(s)
        ln_kernel<false><<<ROWS, 256>>>(s, ln1_g, ln1_b, sn);
        // v = sn @ Wv[a]^T
        sgemm_tn<false, false, false, false><<<g768, 256>>>(
            sn, Wv_a, nullptr, nullptr, v, nullptr, ROWS, MM, MM);
        // imv = exclusive cumsum of v over token dim (per batch n)
        scan_kernel<<<(NB * MM) / 256, 256>>>(v, imv);
        // s = imv @ Wo[a]^T + s
        sgemm_tn<false, true, false, false><<<g768, 256>>>(
            imv, Wo_a, nullptr, nullptr, s, s, ROWS, MM, MM);
        // sn(t) = LN2(s) + s
        ln_kernel<true><<<ROWS, 256>>>(s, ln2_g, ln2_b, sn);
        // h = GELU(t @ fc1^T + b1)
        sgemm_tn<true, false, true, false><<<g3072, 256>>>(
            sn, fc1_w, fc1_b, nullptr, h, nullptr, ROWS, HID, MM);
        // s = h @ fc2^T + b2   (last stage writes directly to d_out)
        float* dst = (a == TK - 1) ? out : s;
        sgemm_tn<true, false, false, false><<<g768, 256>>>(
            h, fc2_w, fc2_b, nullptr, dst, nullptr, ROWS, MM, HID);
    }
}

// round 9
// speedup vs baseline: 1.5223x; 1.5223x over previous
#include <cuda_runtime.h>
#include <cuda_bf16.h>
#include <math.h>
#include <stdint.h>

#define NB   16
#define SQ   256
#define MM   768
#define TK   10
#define ROWS (NB*SQ)        // 4096
#define HID  (4*MM)         // 3072
#define EPS  1e-5f

// ---------------- static scratch (allocation-free rule) ----------------
__device__ float g_s [ROWS*MM];
__device__ float g_v [ROWS*MM];
__device__ float g_pe[SQ*MM];

__device__ __nv_bfloat16 g_xh [ROWS*MM],  g_xl [ROWS*MM];
__device__ __nv_bfloat16 g_snh[ROWS*MM],  g_snl[ROWS*MM];
__device__ __nv_bfloat16 g_imh[ROWS*MM],  g_iml[ROWS*MM];
__device__ __nv_bfloat16 g_hh [ROWS*HID], g_hl [ROWS*HID];

__device__ __nv_bfloat16 g_wh [MM*MM],      g_wl [MM*MM];
__device__ __nv_bfloat16 g_wvh[TK*MM*MM],   g_wvl[TK*MM*MM];
__device__ __nv_bfloat16 g_woh[TK*MM*MM],   g_wol[TK*MM*MM];
__device__ __nv_bfloat16 g_f1h[HID*MM],     g_f1l[HID*MM];
__device__ __nv_bfloat16 g_f2h[MM*HID],     g_f2l[MM*HID];

// ---------------- small helpers ----------------------------------------
__device__ __forceinline__ uint32_t s2u(const void* p) {
    uint32_t a;
    asm("{ .reg .u64 t; cvta.to.shared.u64 t, %1; cvt.u32.u64 %0, t; }"
        : "=r"(a) : "l"(p));
    return a;
}
__device__ __forceinline__ void cp16(uint32_t sdst, const void* gsrc) {
    asm volatile("cp.async.cg.shared.global [%0], [%1], 16;"
                 :: "r"(sdst), "l"(gsrc) : "memory");
}
__device__ __forceinline__ void cp_commit() {
    asm volatile("cp.async.commit_group;" ::: "memory");
}
template <int N>
__device__ __forceinline__ void cp_wait() {
    asm volatile("cp.async.wait_group %0;" :: "n"(N) : "memory");
}
__device__ __forceinline__ void ldmx4(uint32_t& r0, uint32_t& r1,
                                      uint32_t& r2, uint32_t& r3, uint32_t a) {
    asm volatile("ldmatrix.sync.aligned.m8n8.x4.shared.b16 {%0,%1,%2,%3}, [%4];"
                 : "=r"(r0), "=r"(r1), "=r"(r2), "=r"(r3) : "r"(a));
}
__device__ __forceinline__ void mma16816(float* d, const uint32_t* a,
                                         uint32_t b0, uint32_t b1) {
    asm volatile("mma.sync.aligned.m16n8k16.row.col.f32.bf16.bf16.f32 "
                 "{%0,%1,%2,%3}, {%4,%5,%6,%7}, {%8,%9}, {%0,%1,%2,%3};"
                 : "+f"(d[0]), "+f"(d[1]), "+f"(d[2]), "+f"(d[3])
                 : "r"(a[0]), "r"(a[1]), "r"(a[2]), "r"(a[3]),
                   "r"(b0), "r"(b1));
}

// ---------------- positional encoding (fp64, matches reference) --------
__global__ void pe_kernel(float* __restrict__ pe) {
    int idx = blockIdx.x * 256 + threadIdx.x;
    if (idx >= SQ * MM) return;
    int j = idx / MM;
    int m = idx % MM;
    int z = m & ~1;
    double ang = (double)j * exp(-((double)(2 * z) / (double)MM) * log(10000.0));
    pe[idx] = (float)((m & 1) ? cos(ang) : sin(ang));
}

// ---------------- fp32 -> (bf16 hi, bf16 lo) split ---------------------
__global__ __launch_bounds__(256) void split_kernel(
    const float* __restrict__ s, __nv_bfloat16* __restrict__ hi,
    __nv_bfloat16* __restrict__ lo, int n)
{
    int i = blockIdx.x * 256 + threadIdx.x;
    if (i >= n) return;
    float x = s[i];
    __nv_bfloat16 h = __float2bfloat16(x);
    hi[i] = h;
    lo[i] = __float2bfloat16(x - __bfloat162float(h));
}

// ---------------- LayerNorm (+optional residual) -> hi/lo bf16 ---------
template <bool ADDRES>
__global__ __launch_bounds__(256) void ln_split_kernel(
    const float* __restrict__ in, const float* __restrict__ g,
    const float* __restrict__ b, __nv_bfloat16* __restrict__ oh,
    __nv_bfloat16* __restrict__ ol)
{
    int r = blockIdx.x;
    int tid = threadIdx.x;
    const float* row = in + (size_t)r * MM;
    float x0 = row[tid], x1 = row[tid + 256], x2 = row[tid + 512];

    __shared__ float sd[256];
    sd[tid] = x0 + x1 + x2;
    __syncthreads();
    #pragma unroll
    for (int o = 128; o > 0; o >>= 1) { if (tid < o) sd[tid] += sd[tid + o]; __syncthreads(); }
    float mu = sd[0] * (1.0f / (float)MM);
    __syncthreads();

    float d0 = x0 - mu, d1 = x1 - mu, d2 = x2 - mu;
    sd[tid] = d0 * d0 + d1 * d1 + d2 * d2;
    __syncthreads();
    #pragma unroll
    for (int o = 128; o > 0; o >>= 1) { if (tid < o) sd[tid] += sd[tid + o]; __syncthreads(); }
    float rstd = rsqrtf(sd[0] * (1.0f / (float)MM) + EPS);

    size_t base = (size_t)r * MM;
    float v0 = d0 * rstd * g[tid]       + b[tid]       + (ADDRES ? x0 : 0.f);
    float v1 = d1 * rstd * g[tid + 256] + b[tid + 256] + (ADDRES ? x1 : 0.f);
    float v2 = d2 * rstd * g[tid + 512] + b[tid + 512] + (ADDRES ? x2 : 0.f);
    __nv_bfloat16 h0 = __float2bfloat16(v0);
    __nv_bfloat16 h1 = __float2bfloat16(v1);
    __nv_bfloat16 h2 = __float2bfloat16(v2);
    oh[base + tid]       = h0; ol[base + tid]       = __float2bfloat16(v0 - __bfloat162float(h0));
    oh[base + tid + 256] = h1; ol[base + tid + 256] = __float2bfloat16(v1 - __bfloat162float(h1));
    oh[base + tid + 512] = h2; ol[base + tid + 512] = __float2bfloat16(v2 - __bfloat162float(h2));
}

// ---------------- exclusive token prefix sum -> hi/lo bf16 -------------
__global__ __launch_bounds__(256) void scan_split_kernel(
    const float* __restrict__ v, __nv_bfloat16* __restrict__ oh,
    __nv_bfloat16* __restrict__ ol)
{
    int idx = blockIdx.x * 256 + threadIdx.x;     // 0..12287 = (n,d)
    int n = idx / MM;
    int d = idx % MM;
    const float* src = v + (size_t)n * SQ * MM + d;
    size_t base = (size_t)n * SQ * MM + d;
    float acc = 0.f;
    #pragma unroll 4
    for (int j = 0; j < SQ; j++) {
        __nv_bfloat16 h = __float2bfloat16(acc);
        oh[base + (size_t)j * MM] = h;
        ol[base + (size_t)j * MM] = __float2bfloat16(acc - __bfloat162float(h));
        acc += src[(size_t)j * MM];
    }
}

// ---------------- HMMA GEMM: C = A @ W^T, bf16x3 split ------------------
// Tile 128x128, BK=32, 8 warps (64x32 each), double-buffered cp.async SMEM.
// SMEM pitch 80B -> ldmatrix 8-row address sets hit disjoint bank quads.
// EPI: 0 = fp32; 1 = fp32+PE; 2 = fp32+residual; 3 = bias+GELU->hi/lo; 4 = fp32+bias.
template <int EPI>
__global__ __launch_bounds__(256, 2) void hmma_gemm(
    const __nv_bfloat16* __restrict__ Ah, const __nv_bfloat16* __restrict__ Al,
    const __nv_bfloat16* __restrict__ Wh, const __nv_bfloat16* __restrict__ Wl,
    const float* __restrict__ bias, const float* __restrict__ extra,
    float* __restrict__ Cf, __nv_bfloat16* __restrict__ Chi,
    __nv_bfloat16* __restrict__ Clo, int Nc, int K)
{
    constexpr int PITCH = 80;            // bytes per 32-bf16 row (64B data + pad)
    constexpr int ATILE = 128 * PITCH;   // 10240
    constexpr int BUF   = 2 * ATILE;     // 20480 (A tile + B tile)
    __shared__ __align__(16) char smem[2 * BUF];   // 40 KB

    const uint32_t sb = s2u(smem);
    const int tid = threadIdx.x, wid = tid >> 5, lane = tid & 31;
    const int tm = blockIdx.y * 128, tn = blockIdx.x * 128;
    const int wm = (wid & 1) * 64;       // warp row offset in tile
    const int wn = (wid >> 1) * 32;      // warp col offset in tile

    const int KC = K / 32;               // chunks per pass
    const int NC = 3 * KC;               // total chunks (3 split passes)

    float acc[4][4][4];
    #pragma unroll
    for (int i = 0; i < 4; i++)
        #pragma unroll
        for (int j = 0; j < 4; j++)
            #pragma unroll
            for (int t = 0; t < 4; t++) acc[i][j][t] = 0.f;

    // per-thread load coordinates (4 cp.async of 16B each per chunk)
    const int lrowA = tid >> 2, lchA = tid & 3;          // A: 128 rows x 4 chunks
    const int lrowB0 = tid >> 2;                         // B same shape

    auto issue = [&](int c, int buf) {
        int pass = c / KC;
        int kk = (c - pass * KC) * 32;
        const __nv_bfloat16* Ap = (pass == 2) ? Al : Ah;
        const __nv_bfloat16* Bp = (pass == 1) ? Wl : Wh;
        uint32_t s0 = sb + buf * BUF;
        // A: rows tid>>2 and (tid>>2)+64
        cp16(s0 + lrowA * PITCH + lchA * 16,
             Ap + (size_t)(tm + lrowA) * K + kk + lchA * 8);
        cp16(s0 + (lrowA + 64) * PITCH + lchA * 16,
             Ap + (size_t)(tm + lrowA + 64) * K + kk + lchA * 8);
        // B
        uint32_t s1 = s0 + ATILE;
        cp16(s1 + lrowB0 * PITCH + lchA * 16,
             Bp + (size_t)(tn + lrowB0) * K + kk + lchA * 8);
        cp16(s1 + (lrowB0 + 64) * PITCH + lchA * 16,
             Bp + (size_t)(tn + lrowB0 + 64) * K + kk + lchA * 8);
        cp_commit();
    };

    issue(0, 0);

    const int lr16 = lane & 15, lh = (lane >> 4) * 16;   // ldmatrix addressing

    for (int c = 0; c < NC; c++) {
        if (c + 1 < NC) { issue(c + 1, (c + 1) & 1); cp_wait<1>(); }
        else            { cp_wait<0>(); }
        __syncthreads();

        uint32_t aB = sb + (c & 1) * BUF;
        uint32_t bB = aB + ATILE;

        #pragma unroll
        for (int k16 = 0; k16 < 2; k16++) {
            uint32_t koff = k16 * 32 + lh;   // bytes within row
            // B fragments: 2 x ldmatrix.x4 -> 4 n-tiles x {k-lo, k-hi}
            uint32_t bf[2][4];
            #pragma unroll
            for (int pr = 0; pr < 2; pr++) {
                uint32_t addr = bB + (uint32_t)(wn + pr * 16 + lr16) * PITCH + koff;
                ldmx4(bf[pr][0], bf[pr][1], bf[pr][2], bf[pr][3], addr);
            }
            // A fragments + MMAs
            #pragma unroll
            for (int mi = 0; mi < 4; mi++) {
                uint32_t af[4];
                uint32_t addr = aB + (uint32_t)(wm + mi * 16 + lr16) * PITCH + koff;
                ldmx4(af[0], af[1], af[2], af[3], addr);
                #pragma unroll
                for (int ni = 0; ni < 4; ni++) {
                    uint32_t b0 = bf[ni >> 1][ni & 1];
                    uint32_t b1 = bf[ni >> 1][2 + (ni & 1)];
                    mma16816(acc[mi][ni], af, b0, b1);
                }
            }
        }
        __syncthreads();
    }

    // ---------------- epilogue (register fragments -> GMEM) -------------
    const int qr = lane >> 2, qc = (lane & 3) * 2;
    #pragma unroll
    for (int mi = 0; mi < 4; mi++) {
        #pragma unroll
        for (int half = 0; half < 2; half++) {          // row, row+8
            int r = tm + wm + mi * 16 + qr + half * 8;
            #pragma unroll
            for (int ni = 0; ni < 4; ni++) {
                int cc = tn + wn + ni * 8 + qc;
                float v0 = acc[mi][ni][half * 2 + 0];
                float v1 = acc[mi][ni][half * 2 + 1];
                if (EPI == 1) {
                    const float* p = extra + (size_t)(r & (SQ - 1)) * MM + cc;
                    v0 += p[0]; v1 += p[1];
                }
                if (EPI == 2) {
                    const float* p = extra + (size_t)r * Nc + cc;
                    v0 += p[0]; v1 += p[1];
                }
                if (EPI >= 3) { v0 += bias[cc]; v1 += bias[cc + 1]; }
                if (EPI == 3) {
                    v0 = 0.5f * v0 * (1.0f + erff(v0 * 0.70710678118654752f));
                    v1 = 0.5f * v1 * (1.0f + erff(v1 * 0.70710678118654752f));
                    __nv_bfloat16 h0 = __float2bfloat16(v0);
                    __nv_bfloat16 h1 = __float2bfloat16(v1);
                    __nv_bfloat162 hh; hh.x = h0; hh.y = h1;
                    *(__nv_bfloat162*)(Chi + (size_t)r * Nc + cc) = hh;
                    __nv_bfloat162 ll;
                    ll.x = __float2bfloat16(v0 - __bfloat162float(h0));
                    ll.y = __float2bfloat16(v1 - __bfloat162float(h1));
                    *(__nv_bfloat162*)(Clo + (size_t)r * Nc + cc) = ll;
                } else {
                    float2 t = make_float2(v0, v1);
                    *(float2*)(Cf + (size_t)r * Nc + cc) = t;
                }
            }
        }
    }
}

// ---------------- launcher ---------------------------------------------
extern "C" void kernel_launch(void* const* d_in, const int* in_sizes, int n_in,
                              void* d_out, int out_size)
{
    (void)in_sizes; (void)n_in; (void)out_size;
    const float* x      = (const float*)d_in[0];
    const float* weight = (const float*)d_in[1];
    // d_in[2]=Wq, d_in[3]=Wk: dead (softmax over size-1 axis == 1)
    const float* Wv     = (const float*)d_in[4];
    const float* Wo     = (const float*)d_in[5];
    const float* ln1_g  = (const float*)d_in[6];
    const float* ln1_b  = (const float*)d_in[7];
    const float* ln2_g  = (const float*)d_in[8];
    const float* ln2_b  = (const float*)d_in[9];
    const float* fc1_w  = (const float*)d_in[10];
    const float* fc1_b  = (const float*)d_in[11];
    const float* fc2_w  = (const float*)d_in[12];
    const float* fc2_b  = (const float*)d_in[13];
    float* out = (float*)d_out;

    float *s, *v, *pe;
    cudaGetSymbolAddress((void**)&s,  g_s);
    cudaGetSymbolAddress((void**)&v,  g_v);
    cudaGetSymbolAddress((void**)&pe, g_pe);
    __nv_bfloat16 *xh,*xl,*snh,*snl,*imh,*iml,*hh,*hl;
    __nv_bfloat16 *wh,*wl,*wvh,*wvl,*woh,*wol,*f1h,*f1l,*f2h,*f2l;
    cudaGetSymbolAddress((void**)&xh,  g_xh);  cudaGetSymbolAddress((void**)&xl,  g_xl);
    cudaGetSymbolAddress((void**)&snh, g_snh); cudaGetSymbolAddress((void**)&snl, g_snl);
    cudaGetSymbolAddress((void**)&imh, g_imh); cudaGetSymbolAddress((void**)&iml, g_iml);
    cudaGetSymbolAddress((void**)&hh,  g_hh);  cudaGetSymbolAddress((void**)&hl,  g_hl);
    cudaGetSymbolAddress((void**)&wh,  g_wh);  cudaGetSymbolAddress((void**)&wl,  g_wl);
    cudaGetSymbolAddress((void**)&wvh, g_wvh); cudaGetSymbolAddress((void**)&wvl, g_wvl);
    cudaGetSymbolAddress((void**)&woh, g_woh); cudaGetSymbolAddress((void**)&wol, g_wol);
    cudaGetSymbolAddress((void**)&f1h, g_f1h); cudaGetSymbolAddress((void**)&f1l, g_f1l);
    cudaGetSymbolAddress((void**)&f2h, g_f2h); cudaGetSymbolAddress((void**)&f2l, g_f2l);

    dim3 g768(MM / 128, ROWS / 128);    // (6, 32)
    dim3 g3072(HID / 128, ROWS / 128);  // (24, 32)

    pe_kernel<<<(SQ * MM + 255) / 256, 256>>>(pe);

    auto SPL = [](const float* src, __nv_bfloat16* h, __nv_bfloat16* l, int n) {
        split_kernel<<<(n + 255) / 256, 256>>>(src, h, l, n);
    };
    SPL(x,      xh,  xl,  ROWS * MM);
    SPL(weight, wh,  wl,  MM * MM);
    SPL(Wv,     wvh, wvl, TK * MM * MM);
    SPL(Wo,     woh, wol, TK * MM * MM);
    SPL(fc1_w,  f1h, f1l, HID * MM);
    SPL(fc2_w,  f2h, f2l, MM * HID);

    // prelude: s = x @ weight^T + PE
    hmma_gemm<1><<<g768, 256>>>(xh, xl, wh, wl, nullptr, pe,
                                s, nullptr, nullptr, MM, MM);

    for (int a = 0; a < TK; a++) {
        size_t off = (size_t)a * MM * MM;
        // sn = LN1(s) (hi/lo)
        ln_split_kernel<false><<<ROWS, 256>>>(s, ln1_g, ln1_b, snh, snl);
        // v = sn @ Wv[a]^T (fp32)
        hmma_gemm<0><<<g768, 256>>>(snh, snl, wvh + off, wvl + off,
                                    nullptr, nullptr, v, nullptr, nullptr, MM, MM);
        // imv = exclusive cumsum over tokens (hi/lo)
        scan_split_kernel<<<(NB * MM) / 256, 256>>>(v, imh, iml);
        // s = imv @ Wo[a]^T + s
        hmma_gemm<2><<<g768, 256>>>(imh, iml, woh + off, wol + off,
                                    nullptr, s, s, nullptr, nullptr, MM, MM);
        // t = LN2(s) + s (hi/lo)
        ln_split_kernel<true><<<ROWS, 256>>>(s, ln2_g, ln2_b, snh, snl);
        // h = GELU(t @ fc1^T + b1) (hi/lo)
        hmma_gemm<3><<<g3072, 256>>>(snh, snl, f1h, f1l, fc1_b, nullptr,
                                     nullptr, hh, hl, HID, MM);
        // s = h @ fc2^T + b2 (last stage -> d_out)
        float* dst = (a == TK - 1) ? out : s;
        hmma_gemm<4><<<g768, 256>>>(hh, hl, f2h, f2l, fc2_b, nullptr,
                                    dst, nullptr, nullptr, MM, HID);
    }
}